// round 8
// baseline (speedup 1.0000x reference)
#include <cuda_runtime.h>

#define RES 256
#define CELLS (RES*RES)
#define NCH 32
#define ACCSZ (CELLS*NCH)
#define NPLANE 3
#define NG 500000
#define NTILE 16              // tiles per axis (16x16 px each)
#define TPL (NTILE*NTILE)     // tiles per plane = 256
#define NTILES (NPLANE*TPL)   // 768
#define FULLMASK 0xFFFFFFFFu

// Scratch (device globals: allocation-free rule)
__device__ float  g_acc [NPLANE*ACCSZ];   // [plane][cell][ch]
__device__ float  g_cnt [NPLANE*CELLS];   // [plane][cell]
__device__ float  g_newT[NPLANE*ACCSZ];   // [plane][ch][cell]  (transposed, /count)
__device__ double g_sum [NPLANE];
__device__ double g_ss  [NPLANE];
__device__ int    g_hist  [NTILES];
__device__ int    g_base  [NTILES];
__device__ int    g_cursor[NTILES];
__device__ float4 g_recs[NPLANE*NG];      // {px, py, gid_as_float, unused}

// ---------------------------------------------------------------- helpers
__device__ __forceinline__ void plane_xy_of(float x, float y, float z, int p,
                                            float& px, float& py) {
    px = (p == 2) ? y : x;     // xy:(x,y) xz:(x,z) yz:(y,z)
    py = (p == 0) ? y : z;
}

__device__ __forceinline__ void grid_coords(const float* xyz, int g,
                                            float& x, float& y, float& z) {
    float gx = __ldg(xyz + 3*g + 0);
    float gy = __ldg(xyz + 3*g + 1);
    float gz = __ldg(xyz + 3*g + 2);
    x = fminf(fmaxf((gx + 1.f) * 0.5f, 0.f), 0.999f) * (float)(RES - 1);
    y = fminf(fmaxf((gy + 1.f) * 0.5f, 0.f), 0.999f) * (float)(RES - 1);
    z = fminf(fmaxf((gz + 1.f) * 0.5f, 0.f), 0.999f) * (float)(RES - 1);
}

// ---------------------------------------------------------------- zero
__global__ void k_zero() {
    int i = blockIdx.x * blockDim.x + threadIdx.x;
    int stride = gridDim.x * blockDim.x;
    float4 zz = make_float4(0.f, 0.f, 0.f, 0.f);
    float4* a = (float4*)g_acc;
    float4* c = (float4*)g_cnt;
    for (int j = i; j < NPLANE*ACCSZ/4; j += stride) a[j] = zz;
    for (int j = i; j < NPLANE*CELLS/4; j += stride) c[j] = zz;
    if (i < NTILES) g_hist[i] = 0;
    if (i < NPLANE) { g_sum[i] = 0.0; g_ss[i] = 0.0; }
}

// ---------------------------------------------------------------- histogram
__global__ void k_hist(const float* __restrict__ xyz, int n) {
    int g = blockIdx.x * blockDim.x + threadIdx.x;
    if (g >= n) return;
    float x, y, z;  grid_coords(xyz, g, x, y, z);
    #pragma unroll
    for (int p = 0; p < 3; p++) {
        float px, py;  plane_xy_of(x, y, z, p, px, py);
        int ix0 = min(max((int)floorf(px), 0), RES-1);
        int iy0 = min(max((int)floorf(py), 0), RES-1);
        int tile = (iy0 >> 4) * NTILE + (ix0 >> 4);
        atomicAdd(&g_hist[p*TPL + tile], 1);
    }
}

// ---------------------------------------------------------------- exclusive scan (768, one block)
__global__ void k_scan() {
    int tid  = threadIdx.x;          // 768 threads
    int lane = tid & 31, wid = tid >> 5;
    int v = g_hist[tid];
    int x = v;
    #pragma unroll
    for (int o = 1; o < 32; o <<= 1) {
        int y = __shfl_up_sync(FULLMASK, x, o);
        if (lane >= o) x += y;
    }
    __shared__ int ws[24];
    if (lane == 31) ws[wid] = x;
    __syncthreads();
    if (wid == 0) {
        int s = (lane < 24) ? ws[lane] : 0;
        int inc = s;
        #pragma unroll
        for (int o = 1; o < 32; o <<= 1) {
            int y = __shfl_up_sync(FULLMASK, inc, o);
            if (lane >= o) inc += y;
        }
        if (lane < 24) ws[lane] = inc - s;   // exclusive warp offset
    }
    __syncthreads();
    int excl = x - v + ws[wid];
    g_base[tid]   = excl;
    g_cursor[tid] = excl;
}

// ---------------------------------------------------------------- place records
__global__ void k_place(const float* __restrict__ xyz, int n) {
    int g = blockIdx.x * blockDim.x + threadIdx.x;
    if (g >= n) return;
    float x, y, z;  grid_coords(xyz, g, x, y, z);
    #pragma unroll
    for (int p = 0; p < 3; p++) {
        float px, py;  plane_xy_of(x, y, z, p, px, py);
        int ix0 = min(max((int)floorf(px), 0), RES-1);
        int iy0 = min(max((int)floorf(py), 0), RES-1);
        int tile = (iy0 >> 4) * NTILE + (ix0 >> 4);
        int pos  = atomicAdd(&g_cursor[p*TPL + tile], 1);
        g_recs[pos] = make_float4(px, py, __int_as_float(g), 0.f);
    }
}

// ---------------------------------------------------------------- accumulate per tile
// block = one (plane, tile). smem acc 17x17x32, bank = channel (conflict-free).
__global__ void k_accum(const float* __restrict__ feats) {
    int b    = blockIdx.x;            // 0..767
    int p    = b >> 8;
    int tile = b & 255;
    int tx0  = (tile & 15) << 4;
    int ty0  = (tile >> 4) << 4;

    __shared__ float sacc[17*17*NCH];  // 36.1 KB
    __shared__ float scnt[17*17];

    int tid = threadIdx.x;             // 256
    for (int i = tid; i < 17*17*NCH; i += 256) sacc[i] = 0.f;
    for (int i = tid; i < 17*17;     i += 256) scnt[i] = 0.f;
    __syncthreads();

    int start = g_base[b];
    int end   = start + g_hist[b];
    int wid   = tid >> 5;
    int lane  = tid & 31;

    for (int i = start + wid; i < end; i += 8) {
        float4 r = g_recs[i];          // broadcast load
        float px = r.x, py = r.y;
        int   gid = __float_as_int(r.z);

        int ix0 = (int)floorf(px);
        int iy0 = (int)floorf(py);
        int ix0c = min(max(ix0, 0), RES-1);
        int ix1c = min(ix0 + 1,    RES-1);
        int iy0c = min(max(iy0, 0), RES-1);
        int iy1c = min(iy0 + 1,    RES-1);

        float wx0 = fminf(fmaxf((float)ix1c - px, 0.f), 1.f);
        float wx1 = fminf(fmaxf(px - (float)ix0c, 0.f), 1.f);
        float wy0 = fminf(fmaxf((float)iy1c - py, 0.f), 1.f);
        float wy1 = fminf(fmaxf(py - (float)iy0c, 0.f), 1.f);

        int lx0 = ix0c - tx0;              // 0..15
        int ly0 = iy0c - ty0;
        int lx1 = lx0 + (ix1c - ix0c);     // 0..16
        int ly1 = ly0 + (iy1c - iy0c);

        int c00 = (ly0*17 + lx0)*NCH;
        int c01 = (ly1*17 + lx0)*NCH;      // ref l1: (y1, x0)
        int c10 = (ly0*17 + lx1)*NCH;      // ref l2: (y0, x1)
        int c11 = (ly1*17 + lx1)*NCH;

        float f = __ldg(feats + (size_t)gid*96 + p*32 + lane);
        atomicAdd(&sacc[c00 + lane], f*(wx0*wy0));
        atomicAdd(&sacc[c01 + lane], f*(wx0*wy1));
        atomicAdd(&sacc[c10 + lane], f*(wx1*wy0));
        atomicAdd(&sacc[c11 + lane], f*(wx1*wy1));
        if (lane < 4) {
            int cc = (lane == 0) ? c00 : (lane == 1) ? c01 : (lane == 2) ? c10 : c11;
            atomicAdd(&scnt[cc/NCH], 1.0f);
        }
    }
    __syncthreads();

    // flush: coalesced global atomics (128B lines: consecutive tid = consecutive ch)
    for (int idx = tid; idx < 17*17*NCH; idx += 256) {
        float v = sacc[idx];
        if (v != 0.f) {
            int cell = idx >> 5;           // 0..288
            int ch   = idx & 31;
            int ly = cell / 17, lx = cell - ly*17;
            int gx = tx0 + lx, gy = ty0 + ly;
            if (gx < RES && gy < RES)
                atomicAdd(g_acc + (size_t)p*ACCSZ + ((size_t)(gy*RES + gx))*NCH + ch, v);
        }
    }
    for (int cell = tid; cell < 17*17; cell += 256) {
        float v = scnt[cell];
        if (v != 0.f) {
            int ly = cell / 17, lx = cell - ly*17;
            int gx = tx0 + lx, gy = ty0 + ly;
            if (gx < RES && gy < RES)
                atomicAdd(g_cnt + p*CELLS + gy*RES + gx, v);
        }
    }
}

// ---------------------------------------------------------------- reduce + transpose
__global__ void k_reduce() {
    int p    = blockIdx.y;
    int cell = blockIdx.x * blockDim.x + threadIdx.x;

    float cnt = g_cnt[p*CELLS + cell];
    float inv = 1.f / (cnt + 1e-6f);
    const float4* a = (const float4*)(g_acc + (size_t)p*ACCSZ + (size_t)cell*NCH);
    float* nt = g_newT + (size_t)p*ACCSZ;

    float s = 0.f, ss = 0.f;
    #pragma unroll
    for (int i = 0; i < 8; i++) {
        float4 v = a[i];
        float n0 = v.x*inv, n1 = v.y*inv, n2 = v.z*inv, n3 = v.w*inv;
        s  += n0 + n1 + n2 + n3;
        ss += n0*n0 + n1*n1 + n2*n2 + n3*n3;
        nt[(size_t)(i*4+0)*CELLS + cell] = n0;
        nt[(size_t)(i*4+1)*CELLS + cell] = n1;
        nt[(size_t)(i*4+2)*CELLS + cell] = n2;
        nt[(size_t)(i*4+3)*CELLS + cell] = n3;
    }

    double ds = (double)s, dss = (double)ss;
    #pragma unroll
    for (int off = 16; off; off >>= 1) {
        ds  += __shfl_down_sync(FULLMASK, ds,  off);
        dss += __shfl_down_sync(FULLMASK, dss, off);
    }
    __shared__ double shs[8], shss[8];
    int wid = threadIdx.x >> 5;
    if ((threadIdx.x & 31) == 0) { shs[wid] = ds; shss[wid] = dss; }
    __syncthreads();
    if (threadIdx.x == 0) {
        double t = 0.0, tt = 0.0;
        for (int i = 0; i < 8; i++) { t += shs[i]; tt += shss[i]; }
        atomicAdd(&g_sum[p], t);
        atomicAdd(&g_ss[p], tt);
    }
}

// ---------------------------------------------------------------- normalize + blur + residual
// (R6 measured-best form: column-sliding, smem double-buffered rows)
#define STRIP 32
__global__ void k_blur(const float* __restrict__ p_xy,
                       const float* __restrict__ p_xz,
                       const float* __restrict__ p_yz,
                       const float* __restrict__ lnw,
                       const float* __restrict__ lnb,
                       float* __restrict__ out) {
    const float W0 = 0.054488684549642945f;
    const float W1 = 0.2442013422000340f;
    const float W2 = 0.4026199464998460f;

    int pc = blockIdx.y;
    int p  = pc >> 5;
    int c  = pc & 31;
    int x  = threadIdx.x;

    double nelem = (double)ACCSZ;
    double mu_d  = g_sum[p] / nelem;
    double var_d = g_ss[p] / nelem - mu_d * mu_d;
    float mu  = (float)mu_d;
    float inv = (float)(1.0 / sqrt(var_d + 1e-5));

    const float* nt    = g_newT + (size_t)p*ACCSZ + (size_t)c*CELLS;
    const float* lw    = lnw + (size_t)c*CELLS;
    const float* lb    = lnb + (size_t)c*CELLS;
    const float* plane = ((p == 0) ? p_xy : (p == 1) ? p_xz : p_yz) + (size_t)c*CELLS;
    float*       o     = out + (size_t)p*ACCSZ + (size_t)c*CELLS;

    __shared__ float s[2][260];
    if (x < 2)    { s[0][x] = 0.f;     s[1][x] = 0.f; }
    if (x >= 254) { s[0][x + 4] = 0.f; s[1][x + 4] = 0.f; }

    int y0 = blockIdx.x * STRIP;

    auto loadrow = [&](int y) -> float {
        if ((unsigned)y < (unsigned)RES) {
            int lin = y*RES + x;
            return (nt[lin] - mu) * inv * lw[lin] + lb[lin];
        }
        return 0.f;
    };

    float vA = loadrow(y0 - 2);
    float vB = loadrow(y0 - 1);

    float h0 = 0.f, h1 = 0.f, h2 = 0.f, h3 = 0.f, h4 = 0.f;
    int parity = 0;

    #pragma unroll 4
    for (int i = 0; i < STRIP + 4; i++) {
        int yh = y0 - 2 + i;
        float v = vA;
        vA = vB;
        vB = loadrow(yh + 2);

        s[parity][x + 2] = v;
        __syncthreads();
        float h = W0*(s[parity][x]   + s[parity][x+4])
                + W1*(s[parity][x+1] + s[parity][x+3])
                + W2* s[parity][x+2];
        parity ^= 1;

        h0 = h1; h1 = h2; h2 = h3; h3 = h4; h4 = h;

        if (i >= 4) {
            int yo = yh - 2;
            float r = W0*(h0 + h4) + W1*(h1 + h3) + W2*h2;
            int lin = yo*RES + x;
            o[lin] = r + plane[lin];
        }
    }
}

// ---------------------------------------------------------------- launch
extern "C" void kernel_launch(void* const* d_in, const int* in_sizes, int n_in,
                              void* d_out, int out_size) {
    const float* plane_xy = (const float*)d_in[0];
    const float* plane_xz = (const float*)d_in[1];
    const float* plane_yz = (const float*)d_in[2];
    const float* ln_w     = (const float*)d_in[3];
    const float* ln_b     = (const float*)d_in[4];
    const float* feats    = (const float*)d_in[5];
    const float* xyz      = (const float*)d_in[6];
    float* out = (float*)d_out;
    int n = in_sizes[6] / 3;   // 500000
    if (n > NG) n = NG;

    k_zero<<<1024, 256>>>();
    k_hist <<<(n + 255)/256, 256>>>(xyz, n);
    k_scan <<<1, NTILES>>>();
    k_place<<<(n + 255)/256, 256>>>(xyz, n);
    k_accum<<<NTILES, 256>>>(feats);
    k_reduce<<<dim3(CELLS/256, NPLANE), 256>>>();
    k_blur<<<dim3(RES/STRIP, NPLANE*NCH), 256>>>(
        plane_xy, plane_xz, plane_yz, ln_w, ln_b, out);
}

// round 9
// speedup vs baseline: 3.5903x; 3.5903x over previous
#include <cuda_runtime.h>

#define RES 256
#define CELLS (RES*RES)
#define NCH 32
#define ACCSZ (CELLS*NCH)
#define NPLANE 3
#define FULLMASK 0xFFFFFFFFu

// Scratch (device globals: allocation-free rule)
__device__ float  g_acc [NPLANE*ACCSZ];   // [plane][cell][ch]
__device__ float  g_cnt [NPLANE*CELLS];   // [plane][cell]
__device__ float  g_newT[NPLANE*ACCSZ];   // [plane][ch][cell]  (transposed, /count)
__device__ double g_sum [NPLANE];
__device__ double g_ss  [NPLANE];

// ---------------------------------------------------------------- zero (float4)
__global__ void k_zero() {
    int i = blockIdx.x * blockDim.x + threadIdx.x;
    int stride = gridDim.x * blockDim.x;
    float4 z = make_float4(0.f, 0.f, 0.f, 0.f);
    float4* a = (float4*)g_acc;
    float4* c = (float4*)g_cnt;
    for (int j = i; j < NPLANE*ACCSZ/4; j += stride) a[j] = z;
    for (int j = i; j < NPLANE*CELLS/4; j += stride) c[j] = z;
    if (i < NPLANE) { g_sum[i] = 0.0; g_ss[i] = 0.0; }
}

// ---------------------------------------------------------------- scatter
// one warp per gaussian; lane = channel. 4 coalesced 128B RED lines per plane.
// (measured best: LTS RMW byte-bound floor)
__global__ void k_scatter(const float* __restrict__ xyz,
                          const float* __restrict__ feats, int n) {
    int w    = (blockIdx.x * blockDim.x + threadIdx.x) >> 5;
    int lane = threadIdx.x & 31;
    if (w >= n) return;

    float gx = __ldg(xyz + 3*w + 0);
    float gy = __ldg(xyz + 3*w + 1);
    float gz = __ldg(xyz + 3*w + 2);
    float x = fminf(fmaxf((gx + 1.f) * 0.5f, 0.f), 0.999f) * (float)(RES - 1);
    float y = fminf(fmaxf((gy + 1.f) * 0.5f, 0.f), 0.999f) * (float)(RES - 1);
    float z = fminf(fmaxf((gz + 1.f) * 0.5f, 0.f), 0.999f) * (float)(RES - 1);

    #pragma unroll
    for (int p = 0; p < 3; p++) {
        float px = (p == 2) ? y : x;              // xy:(x,y) xz:(x,z) yz:(y,z)
        float py = (p == 0) ? y : z;

        int ix0 = (int)floorf(px);
        int iy0 = (int)floorf(py);
        int ix0c = min(max(ix0, 0), RES-1);
        int ix1c = min(ix0 + 1,    RES-1);
        int iy0c = min(max(iy0, 0), RES-1);
        int iy1c = min(iy0 + 1,    RES-1);

        float wx0 = fminf(fmaxf((float)ix1c - px, 0.f), 1.f);
        float wx1 = fminf(fmaxf(px - (float)ix0c, 0.f), 1.f);
        float wy0 = fminf(fmaxf((float)iy1c - py, 0.f), 1.f);
        float wy1 = fminf(fmaxf(py - (float)iy0c, 0.f), 1.f);

        int l0 = iy0c*RES + ix0c;
        int l1 = iy1c*RES + ix0c;
        int l2 = iy0c*RES + ix1c;
        int l3 = iy1c*RES + ix1c;
        float w00 = wx0*wy0, w01 = wx0*wy1, w10 = wx1*wy0, w11 = wx1*wy1;

        float f = __ldg(feats + (size_t)w*96 + p*32 + lane);
        float* base = g_acc + (size_t)p*ACCSZ;
        atomicAdd(base + (size_t)l0*NCH + lane, f*w00);
        atomicAdd(base + (size_t)l1*NCH + lane, f*w01);
        atomicAdd(base + (size_t)l2*NCH + lane, f*w10);
        atomicAdd(base + (size_t)l3*NCH + lane, f*w11);

        if (lane < 4) {
            int ll = (lane == 0) ? l0 : (lane == 1) ? l1 : (lane == 2) ? l2 : l3;
            atomicAdd(g_cnt + p*CELLS + ll, 1.0f);
        }
    }
}

// ---------------------------------------------------------------- reduce + transpose
__global__ void k_reduce() {
    int p    = blockIdx.y;
    int cell = blockIdx.x * blockDim.x + threadIdx.x;

    float cnt = g_cnt[p*CELLS + cell];
    float inv = 1.f / (cnt + 1e-6f);
    const float4* a = (const float4*)(g_acc + (size_t)p*ACCSZ + (size_t)cell*NCH);
    float* nt = g_newT + (size_t)p*ACCSZ;

    float s = 0.f, ss = 0.f;
    #pragma unroll
    for (int i = 0; i < 8; i++) {
        float4 v = a[i];
        float n0 = v.x*inv, n1 = v.y*inv, n2 = v.z*inv, n3 = v.w*inv;
        s  += n0 + n1 + n2 + n3;
        ss += n0*n0 + n1*n1 + n2*n2 + n3*n3;
        nt[(size_t)(i*4+0)*CELLS + cell] = n0;
        nt[(size_t)(i*4+1)*CELLS + cell] = n1;
        nt[(size_t)(i*4+2)*CELLS + cell] = n2;
        nt[(size_t)(i*4+3)*CELLS + cell] = n3;
    }

    double ds = (double)s, dss = (double)ss;
    #pragma unroll
    for (int off = 16; off; off >>= 1) {
        ds  += __shfl_down_sync(FULLMASK, ds,  off);
        dss += __shfl_down_sync(FULLMASK, dss, off);
    }
    __shared__ double shs[8], shss[8];
    int wid = threadIdx.x >> 5;
    if ((threadIdx.x & 31) == 0) { shs[wid] = ds; shss[wid] = dss; }
    __syncthreads();
    if (threadIdx.x == 0) {
        double t = 0.0, tt = 0.0;
        for (int i = 0; i < 8; i++) { t += shs[i]; tt += shss[i]; }
        atomicAdd(&g_sum[p], t);
        atomicAdd(&g_ss[p], tt);
    }
}

// ---------------------------------------------------------------- normalize + blur + residual
// Column-sliding blur, STRIP=64: block = 256 threads = full image width, one
// (p, c, 64-row strip). Horizontal 5-tap via double-buffered smem row
// (1 sync/row); vertical 5-tap rolling register window; LN fused at load,
// residual fused at store.
#define STRIP 64
__global__ void k_blur(const float* __restrict__ p_xy,
                       const float* __restrict__ p_xz,
                       const float* __restrict__ p_yz,
                       const float* __restrict__ lnw,
                       const float* __restrict__ lnb,
                       float* __restrict__ out) {
    const float W0 = 0.054488684549642945f;
    const float W1 = 0.2442013422000340f;
    const float W2 = 0.4026199464998460f;

    int pc = blockIdx.y;
    int p  = pc >> 5;
    int c  = pc & 31;
    int x  = threadIdx.x;

    double nelem = (double)ACCSZ;
    double mu_d  = g_sum[p] / nelem;
    double var_d = g_ss[p] / nelem - mu_d * mu_d;
    float mu  = (float)mu_d;
    float inv = (float)(1.0 / sqrt(var_d + 1e-5));

    const float* nt    = g_newT + (size_t)p*ACCSZ + (size_t)c*CELLS;
    const float* lw    = lnw + (size_t)c*CELLS;
    const float* lb    = lnb + (size_t)c*CELLS;
    const float* plane = ((p == 0) ? p_xy : (p == 1) ? p_xz : p_yz) + (size_t)c*CELLS;
    float*       o     = out + (size_t)p*ACCSZ + (size_t)c*CELLS;

    __shared__ float s[2][260];
    if (x < 2)    { s[0][x] = 0.f;     s[1][x] = 0.f; }
    if (x >= 254) { s[0][x + 4] = 0.f; s[1][x + 4] = 0.f; }

    int y0 = blockIdx.x * STRIP;

    auto loadrow = [&](int y) -> float {
        if ((unsigned)y < (unsigned)RES) {
            int lin = y*RES + x;
            return (nt[lin] - mu) * inv * lw[lin] + lb[lin];
        }
        return 0.f;
    };

    float vA = loadrow(y0 - 2);
    float vB = loadrow(y0 - 1);

    float h0 = 0.f, h1 = 0.f, h2 = 0.f, h3 = 0.f, h4 = 0.f;
    int parity = 0;

    #pragma unroll 4
    for (int i = 0; i < STRIP + 4; i++) {
        int yh = y0 - 2 + i;
        float v = vA;
        vA = vB;
        vB = loadrow(yh + 2);

        s[parity][x + 2] = v;
        __syncthreads();
        float h = W0*(s[parity][x]   + s[parity][x+4])
                + W1*(s[parity][x+1] + s[parity][x+3])
                + W2* s[parity][x+2];
        parity ^= 1;

        h0 = h1; h1 = h2; h2 = h3; h3 = h4; h4 = h;

        if (i >= 4) {
            int yo = yh - 2;
            float r = W0*(h0 + h4) + W1*(h1 + h3) + W2*h2;
            int lin = yo*RES + x;
            o[lin] = r + plane[lin];
        }
    }
}

// ---------------------------------------------------------------- launch
extern "C" void kernel_launch(void* const* d_in, const int* in_sizes, int n_in,
                              void* d_out, int out_size) {
    const float* plane_xy = (const float*)d_in[0];
    const float* plane_xz = (const float*)d_in[1];
    const float* plane_yz = (const float*)d_in[2];
    const float* ln_w     = (const float*)d_in[3];
    const float* ln_b     = (const float*)d_in[4];
    const float* feats    = (const float*)d_in[5];
    const float* xyz      = (const float*)d_in[6];
    float* out = (float*)d_out;
    int n = in_sizes[6] / 3;   // 500000

    k_zero<<<1024, 256>>>();
    {
        int threads = 256;
        long long total = (long long)n * 32;
        int blocks = (int)((total + threads - 1) / threads);
        k_scatter<<<blocks, threads>>>(xyz, feats, n);
    }
    k_reduce<<<dim3(CELLS/256, NPLANE), 256>>>();
    // 384 blocks = 4 strips x (3 planes x 32 ch)
    k_blur<<<dim3(RES/STRIP, NPLANE*NCH), 256>>>(
        plane_xy, plane_xz, plane_yz, ln_w, ln_b, out);
}

// round 10
// speedup vs baseline: 4.1501x; 1.1559x over previous
#include <cuda_runtime.h>

#define RES 256
#define CELLS (RES*RES)
#define NCH 32
#define ACCSZ (CELLS*NCH)
#define NPLANE 3
#define FULLMASK 0xFFFFFFFFu

// Scratch (device globals: allocation-free rule)
__device__ float  g_acc [NPLANE*ACCSZ];   // [plane][cell][ch]
__device__ float  g_cnt [NPLANE*CELLS];   // [plane][cell]
__device__ float  g_newT[NPLANE*ACCSZ];   // [plane][ch][cell]  (transposed, /count)
__device__ double g_sum [NPLANE];
__device__ double g_ss  [NPLANE];

// ---------------------------------------------------------------- zero (float4)
__global__ void k_zero() {
    int i = blockIdx.x * blockDim.x + threadIdx.x;
    int stride = gridDim.x * blockDim.x;
    float4 z = make_float4(0.f, 0.f, 0.f, 0.f);
    float4* a = (float4*)g_acc;
    float4* c = (float4*)g_cnt;
    for (int j = i; j < NPLANE*ACCSZ/4; j += stride) a[j] = z;
    for (int j = i; j < NPLANE*CELLS/4; j += stride) c[j] = z;
    if (i < NPLANE) { g_sum[i] = 0.0; g_ss[i] = 0.0; }
}

// ---------------------------------------------------------------- scatter
// one warp per gaussian; lane = channel. 4 coalesced 128B RED lines per plane.
// (measured best: LTS RMW byte-bound floor)
__global__ void k_scatter(const float* __restrict__ xyz,
                          const float* __restrict__ feats, int n) {
    int w    = (blockIdx.x * blockDim.x + threadIdx.x) >> 5;
    int lane = threadIdx.x & 31;
    if (w >= n) return;

    float gx = __ldg(xyz + 3*w + 0);
    float gy = __ldg(xyz + 3*w + 1);
    float gz = __ldg(xyz + 3*w + 2);
    float x = fminf(fmaxf((gx + 1.f) * 0.5f, 0.f), 0.999f) * (float)(RES - 1);
    float y = fminf(fmaxf((gy + 1.f) * 0.5f, 0.f), 0.999f) * (float)(RES - 1);
    float z = fminf(fmaxf((gz + 1.f) * 0.5f, 0.f), 0.999f) * (float)(RES - 1);

    #pragma unroll
    for (int p = 0; p < 3; p++) {
        float px = (p == 2) ? y : x;              // xy:(x,y) xz:(x,z) yz:(y,z)
        float py = (p == 0) ? y : z;

        int ix0 = (int)floorf(px);
        int iy0 = (int)floorf(py);
        int ix0c = min(max(ix0, 0), RES-1);
        int ix1c = min(ix0 + 1,    RES-1);
        int iy0c = min(max(iy0, 0), RES-1);
        int iy1c = min(iy0 + 1,    RES-1);

        float wx0 = fminf(fmaxf((float)ix1c - px, 0.f), 1.f);
        float wx1 = fminf(fmaxf(px - (float)ix0c, 0.f), 1.f);
        float wy0 = fminf(fmaxf((float)iy1c - py, 0.f), 1.f);
        float wy1 = fminf(fmaxf(py - (float)iy0c, 0.f), 1.f);

        int l0 = iy0c*RES + ix0c;
        int l1 = iy1c*RES + ix0c;
        int l2 = iy0c*RES + ix1c;
        int l3 = iy1c*RES + ix1c;
        float w00 = wx0*wy0, w01 = wx0*wy1, w10 = wx1*wy0, w11 = wx1*wy1;

        float f = __ldg(feats + (size_t)w*96 + p*32 + lane);
        float* base = g_acc + (size_t)p*ACCSZ;
        atomicAdd(base + (size_t)l0*NCH + lane, f*w00);
        atomicAdd(base + (size_t)l1*NCH + lane, f*w01);
        atomicAdd(base + (size_t)l2*NCH + lane, f*w10);
        atomicAdd(base + (size_t)l3*NCH + lane, f*w11);

        if (lane < 4) {
            int ll = (lane == 0) ? l0 : (lane == 1) ? l1 : (lane == 2) ? l2 : l3;
            atomicAdd(g_cnt + p*CELLS + ll, 1.0f);
        }
    }
}

// ---------------------------------------------------------------- reduce + transpose
__global__ void k_reduce() {
    int p    = blockIdx.y;
    int cell = blockIdx.x * blockDim.x + threadIdx.x;

    float cnt = g_cnt[p*CELLS + cell];
    float inv = 1.f / (cnt + 1e-6f);
    const float4* a = (const float4*)(g_acc + (size_t)p*ACCSZ + (size_t)cell*NCH);
    float* nt = g_newT + (size_t)p*ACCSZ;

    float s = 0.f, ss = 0.f;
    #pragma unroll
    for (int i = 0; i < 8; i++) {
        float4 v = a[i];
        float n0 = v.x*inv, n1 = v.y*inv, n2 = v.z*inv, n3 = v.w*inv;
        s  += n0 + n1 + n2 + n3;
        ss += n0*n0 + n1*n1 + n2*n2 + n3*n3;
        nt[(size_t)(i*4+0)*CELLS + cell] = n0;
        nt[(size_t)(i*4+1)*CELLS + cell] = n1;
        nt[(size_t)(i*4+2)*CELLS + cell] = n2;
        nt[(size_t)(i*4+3)*CELLS + cell] = n3;
    }

    double ds = (double)s, dss = (double)ss;
    #pragma unroll
    for (int off = 16; off; off >>= 1) {
        ds  += __shfl_down_sync(FULLMASK, ds,  off);
        dss += __shfl_down_sync(FULLMASK, dss, off);
    }
    __shared__ double shs[8], shss[8];
    int wid = threadIdx.x >> 5;
    if ((threadIdx.x & 31) == 0) { shs[wid] = ds; shss[wid] = dss; }
    __syncthreads();
    if (threadIdx.x == 0) {
        double t = 0.0, tt = 0.0;
        for (int i = 0; i < 8; i++) { t += shs[i]; tt += shss[i]; }
        atomicAdd(&g_sum[p], t);
        atomicAdd(&g_ss[p], tt);
    }
}

// ---------------------------------------------------------------- normalize + blur + residual
// One-barrier blur: block = 256 threads = full row width, one (p,c,32-row strip).
// Stage whole LN'd 36x256 strip (+2 col zero pads) in smem, sync ONCE, then
// each thread computes 32 outputs from smem: rolling horizontal 5-taps feeding
// a vertical 5-tap window. Residual fused at store.
#define STRIP 32
__global__ void k_blur(const float* __restrict__ p_xy,
                       const float* __restrict__ p_xz,
                       const float* __restrict__ p_yz,
                       const float* __restrict__ lnw,
                       const float* __restrict__ lnb,
                       float* __restrict__ out) {
    const float W0 = 0.054488684549642945f;
    const float W1 = 0.2442013422000340f;
    const float W2 = 0.4026199464998460f;

    int pc = blockIdx.y;
    int p  = pc >> 5;
    int c  = pc & 31;
    int x  = threadIdx.x;

    double nelem = (double)ACCSZ;
    double mu_d  = g_sum[p] / nelem;
    double var_d = g_ss[p] / nelem - mu_d * mu_d;
    float mu  = (float)mu_d;
    float inv = (float)(1.0 / sqrt(var_d + 1e-5));

    const float* nt    = g_newT + (size_t)p*ACCSZ + (size_t)c*CELLS;
    const float* lw    = lnw + (size_t)c*CELLS;
    const float* lb    = lnb + (size_t)c*CELLS;
    const float* plane = ((p == 0) ? p_xy : (p == 1) ? p_xz : p_yz) + (size_t)c*CELLS;
    float*       o     = out + (size_t)p*ACCSZ + (size_t)c*CELLS;

    __shared__ float s[36][260];     // 37.4 KB; cols 0..1 and 258..259 are pads

    // zero column pads (rows handled below: rows outside image load as 0)
    if (x < 36) { s[x][0] = 0.f; s[x][1] = 0.f; s[x][258] = 0.f; s[x][259] = 0.f; }

    int y0 = blockIdx.x * STRIP;

    // stage 36 rows (y0-2 .. y0+33), LN fused; rows outside image = 0
    #pragma unroll
    for (int r = 0; r < 36; r++) {
        int y = y0 - 2 + r;
        float v = 0.f;
        if ((unsigned)y < (unsigned)RES) {
            int lin = y*RES + x;
            v = (nt[lin] - mu) * inv * lw[lin] + lb[lin];
        }
        s[r][x + 2] = v;
    }
    __syncthreads();

    // horizontal 5-tap helper from smem
    auto hrow = [&](int r) -> float {
        return W0*(s[r][x]   + s[r][x+4])
             + W1*(s[r][x+1] + s[r][x+3])
             + W2* s[r][x+2];
    };

    float h0 = hrow(0), h1 = hrow(1), h2 = hrow(2), h3 = hrow(3), h4;

    #pragma unroll
    for (int i = 0; i < STRIP; i++) {
        h4 = hrow(i + 4);
        float r = W0*(h0 + h4) + W1*(h1 + h3) + W2*h2;
        int lin = (y0 + i)*RES + x;
        o[lin] = r + plane[lin];
        h0 = h1; h1 = h2; h2 = h3; h3 = h4;
    }
}

// ---------------------------------------------------------------- launch
extern "C" void kernel_launch(void* const* d_in, const int* in_sizes, int n_in,
                              void* d_out, int out_size) {
    const float* plane_xy = (const float*)d_in[0];
    const float* plane_xz = (const float*)d_in[1];
    const float* plane_yz = (const float*)d_in[2];
    const float* ln_w     = (const float*)d_in[3];
    const float* ln_b     = (const float*)d_in[4];
    const float* feats    = (const float*)d_in[5];
    const float* xyz      = (const float*)d_in[6];
    float* out = (float*)d_out;
    int n = in_sizes[6] / 3;   // 500000

    k_zero<<<1024, 256>>>();
    {
        int threads = 256;
        long long total = (long long)n * 32;
        int blocks = (int)((total + threads - 1) / threads);
        k_scatter<<<blocks, threads>>>(xyz, feats, n);
    }
    k_reduce<<<dim3(CELLS/256, NPLANE), 256>>>();
    // 768 blocks = 8 strips x (3 planes x 32 ch)
    k_blur<<<dim3(RES/STRIP, NPLANE*NCH), 256>>>(
        plane_xy, plane_xz, plane_yz, ln_w, ln_b, out);
}